// round 15
// baseline (speedup 1.0000x reference)
#include <cuda_runtime.h>
#include <cstdint>
#include <float.h>

#define TWO_PI_F 6.283185307179586f
#define M_TOK 16384
#define N_C   768
#define N_CODES 2048
#define MAXC 64
#define GAP_THR 1e-2f
#define WIN 1.5f

// ---------------- scratch (device globals; no allocation allowed) ----------
__device__ float g_Ahi[(size_t)M_TOK * 2048];
__device__ float g_Alo[(size_t)M_TOK * 2048];   // reused as dist[M_TOK][2048] after GEMM1
__device__ float g_xq [(size_t)M_TOK * N_C];
__device__ float g_xqhi[(size_t)M_TOK * N_C];
__device__ float g_whi[(size_t)N_C * 2048];
__device__ float g_wlo[(size_t)N_C * 2048];
__device__ float g_cbhi[(size_t)N_CODES * N_C];
__device__ float g_cblo[(size_t)N_CODES * N_C];
__device__ float g_pwhi[(size_t)N_C * N_C];
__device__ float g_pwlo[(size_t)N_C * N_C];
__device__ float g_cbp[(size_t)N_CODES * N_C];
__device__ float g_cbn[N_CODES];
__device__ unsigned long long g_amin[M_TOK];
__device__ int g_flag[M_TOK];
__device__ int g_ccnt[M_TOK];
__device__ int g_cand[(size_t)M_TOK * MAXC];

// ---------------- small helpers ----------------
__device__ __forceinline__ float tf32r(float v) {
    unsigned u; asm("cvt.rna.tf32.f32 %0, %1;" : "=r"(u) : "f"(v));
    return __uint_as_float(u);
}
__device__ __forceinline__ unsigned int fenc(float f) {
    unsigned int u = __float_as_uint(f);
    return (u & 0x80000000u) ? ~u : (u | 0x80000000u);
}

// ---------------- 2x2 maxpool + 2-way tf32 split ----------------
__global__ __launch_bounds__(256)
void pool_kernel(const float* __restrict__ img) {
    __shared__ float s[8 * 2 * 64];
    const int kchunk = blockIdx.x;
    const int hh = blockIdx.y;
    const int b  = blockIdx.z;
    const int tid = threadIdx.x;
    const int k0 = kchunk * 8;
    #pragma unroll
    for (int q = 0; q < 4; q++) {
        int l = tid + 256 * q;
        int x = l & 63, y = (l >> 6) & 1, kc = l >> 7;
        s[l] = img[((size_t)(b * 2048 + k0 + kc) * 64 + (2 * hh + y)) * 64 + x];
    }
    __syncthreads();
    const int kc = tid & 7, ww = tid >> 3;
    const float* p = &s[kc * 128];
    float v = fmaxf(fmaxf(p[2 * ww], p[2 * ww + 1]),
                    fmaxf(p[64 + 2 * ww], p[64 + 2 * ww + 1]));
    size_t o = (size_t)(b * 1024 + hh * 32 + ww) * 2048 + k0 + kc;
    float h = tf32r(v);
    g_Ahi[o] = h;
    g_Alo[o] = tf32r(v - h);
}

// ---------------- fp32 -> (hi,lo) 2-way tf32 split ----------------
__global__ __launch_bounds__(256)
void split_kernel(const float* __restrict__ src, float* __restrict__ hi,
                  float* __restrict__ lo, int n) {
    int i = blockIdx.x * 256 + threadIdx.x;
    if (i < n) {
        float v = src[i];
        float h = tf32r(v);
        hi[i] = h;
        lo[i] = tf32r(v - h);
    }
}

// ---------------- codebook row norms (IDENTICAL to R1's kernel) ----------
__global__ __launch_bounds__(256)
void cbn_kernel(const float* __restrict__ cb) {
    __shared__ float rb[8];
    const int k = blockIdx.x, tid = threadIdx.x;
    float s = 0.f;
    for (int c = tid; c < 768; c += 256) {
        float v = cb[(size_t)k * 768 + c];
        s = fmaf(v, v, s);
    }
    #pragma unroll
    for (int o = 16; o > 0; o >>= 1) s += __shfl_down_sync(0xffffffffu, s, o);
    if ((tid & 31) == 0) rb[tid >> 5] = s;
    __syncthreads();
    if (tid == 0) {
        float t2 = 0.f;
        #pragma unroll
        for (int q = 0; q < 8; q++) t2 += rb[q];
        g_cbn[k] = t2;
    }
}

// ---------------- mma.sync multi-pass TF32 GEMM (ldmatrix + 3 stages) ------
#define STRF 36
#define TILE_F (128 * STRF)
#define NST 3

__device__ __forceinline__ void mma_tf32(float* d, const unsigned* a, const unsigned* b) {
    asm volatile(
        "mma.sync.aligned.m16n8k8.row.col.f32.tf32.tf32.f32 "
        "{%0,%1,%2,%3}, {%4,%5,%6,%7}, {%8,%9}, {%0,%1,%2,%3};"
        : "+f"(d[0]), "+f"(d[1]), "+f"(d[2]), "+f"(d[3])
        : "r"(a[0]), "r"(a[1]), "r"(a[2]), "r"(a[3]), "r"(b[0]), "r"(b[1]));
}
__device__ __forceinline__ void ldsm_x4(unsigned* r, uint32_t addr) {
    asm volatile("ldmatrix.sync.aligned.m8n8.x4.shared.b16 {%0,%1,%2,%3}, [%4];"
        : "=r"(r[0]), "=r"(r[1]), "=r"(r[2]), "=r"(r[3]) : "r"(addr));
}
__device__ __forceinline__ void ldsm_x2(unsigned* r, uint32_t addr) {
    asm volatile("ldmatrix.sync.aligned.m8n8.x2.shared.b16 {%0,%1}, [%2];"
        : "=r"(r[0]), "=r"(r[1]) : "r"(addr));
}

__device__ __forceinline__ void ld_tile_rm(uint32_t sdst, const float* __restrict__ g,
                                           int base_row, int K, int kt, int tid) {
    #pragma unroll
    for (int i = 0; i < 4; i++) {
        int idx = tid + 256 * i;
        int row = idx >> 3;
        int c = (idx & 7) * 4;
        const float* src = g + (size_t)(base_row + row) * K + kt * 32 + c;
        uint32_t dst = sdst + (uint32_t)(row * STRF + c) * 4u;
        asm volatile("cp.async.cg.shared.global [%0], [%1], 16;"
                     :: "r"(dst), "l"(src) : "memory");
    }
}

template<int MODE, int SPLIT, int NSPLIT>
__global__ __launch_bounds__(256, 1)
void mma_gemm(const float* __restrict__ A0, const float* __restrict__ A1,
              const float* __restrict__ B0, const float* __restrict__ B1,
              float* __restrict__ C, float* __restrict__ Chi,
              const float* __restrict__ bias, int M, int N, int K)
{
    extern __shared__ float smf[];
    const uint32_t sb = (uint32_t)__cvta_generic_to_shared(smf);
    const int STAGE_F = 2 * NSPLIT * TILE_F;

    const float* Ap[2] = {A0, A1};
    const float* Bp[2] = {B0, B1};

    const int tid = threadIdx.x;
    const int wid = tid >> 5, lane = tid & 31;
    const int g = lane >> 2, cid = lane & 3;
    const int wm = wid >> 2, wn = wid & 3;
    const int m0 = wm * 64, n0 = wn * 32;
    const int bm = blockIdx.y * 128, bn = blockIdx.x * 128;
    const int nk = K / 32;

    // per-lane ldmatrix byte offsets
    const int lr = lane & 7;
    const uint32_t aoff = (uint32_t)(((((lane >> 3) & 1) * 8 + lr) * STRF + (lane >> 4) * 4)) * 4u;
    const uint32_t boff = (uint32_t)((lr * STRF + ((lane >> 3) & 1) * 4)) * 4u;

    float acc[4][4][4];
    #pragma unroll
    for (int a = 0; a < 4; a++)
        #pragma unroll
        for (int b = 0; b < 4; b++)
            #pragma unroll
            for (int c = 0; c < 4; c++) acc[a][b][c] = 0.f;

    #pragma unroll
    for (int s = 0; s < NST; s++) {
        uint32_t st = sb + (uint32_t)(s * STAGE_F) * 4u;
        #pragma unroll
        for (int l = 0; l < NSPLIT; l++) {
            ld_tile_rm(st + (uint32_t)(l * TILE_F) * 4u,            Ap[l], bm, K, s, tid);
            ld_tile_rm(st + (uint32_t)((NSPLIT + l) * TILE_F) * 4u, Bp[l], bn, K, s, tid);
        }
        asm volatile("cp.async.commit_group;" ::: "memory");
    }

    for (int kt = 0; kt < nk; kt++) {
        asm volatile("cp.async.wait_group 2;" ::: "memory");
        __syncthreads();
        const uint32_t stg = sb + (uint32_t)((kt % NST) * STAGE_F) * 4u;

        #pragma unroll
        for (int k8 = 0; k8 < 4; k8++) {
            unsigned af[NSPLIT][4][4], bf[NSPLIT][4][2];
            #pragma unroll
            for (int l = 0; l < NSPLIT; l++) {
                #pragma unroll
                for (int mt = 0; mt < 4; mt++)
                    ldsm_x4(af[l][mt],
                            stg + (uint32_t)((l * TILE_F + (m0 + mt * 16) * STRF + k8 * 8)) * 4u + aoff);
                #pragma unroll
                for (int nt = 0; nt < 4; nt++)
                    ldsm_x2(bf[l][nt],
                            stg + (uint32_t)(((NSPLIT + l) * TILE_F + (n0 + nt * 8) * STRF + k8 * 8)) * 4u + boff);
            }
            #pragma unroll
            for (int mt = 0; mt < 4; mt++)
                #pragma unroll
                for (int nt = 0; nt < 4; nt++) {
                    #pragma unroll
                    for (int ia = 0; ia < NSPLIT; ia++)
                        #pragma unroll
                        for (int ib = 0; ib < NSPLIT; ib++)
                            if (ia + ib <= NSPLIT - 1)
                                mma_tf32(acc[mt][nt], af[ia][mt], bf[ib][nt]);
                }
        }
        __syncthreads();
        if (kt + NST < nk) {
            uint32_t st2 = sb + (uint32_t)((kt % NST) * STAGE_F) * 4u;
            #pragma unroll
            for (int l = 0; l < NSPLIT; l++) {
                ld_tile_rm(st2 + (uint32_t)(l * TILE_F) * 4u,            Ap[l], bm, K, kt + NST, tid);
                ld_tile_rm(st2 + (uint32_t)((NSPLIT + l) * TILE_F) * 4u, Bp[l], bn, K, kt + NST, tid);
            }
        }
        asm volatile("cp.async.commit_group;" ::: "memory");
    }

    #pragma unroll
    for (int mt = 0; mt < 4; mt++) {
        #pragma unroll
        for (int rv = 0; rv < 2; rv++) {
            int r = bm + m0 + mt * 16 + g + rv * 8;
            #pragma unroll
            for (int nt = 0; nt < 4; nt++) {
                int col = bn + n0 + nt * 8 + 2 * cid;
                if (MODE == 0) {
                    float v0 = acc[mt][nt][rv * 2 + 0] + bias[col];
                    float v1 = acc[mt][nt][rv * 2 + 1] + bias[col + 1];
                    float2 o; o.x = v0; o.y = v1;
                    *(float2*)(C + (size_t)r * N + col) = o;
                    if (SPLIT) {
                        float2 h;
                        h.x = tf32r(v0);
                        h.y = tf32r(v1);
                        *(float2*)(Chi + (size_t)r * N + col) = h;
                    }
                } else {
                    float2 o;
                    o.x = g_cbn[col]     - 2.0f * acc[mt][nt][rv * 2 + 0];
                    o.y = g_cbn[col + 1] - 2.0f * acc[mt][nt][rv * 2 + 1];
                    *(float2*)(C + (size_t)r * N + col) = o;
                }
            }
        }
    }
}

// ---------------- pass 1: screen + classify (warp-parallel candidates) -----
__global__ __launch_bounds__(256)
void rescue1(const float* __restrict__ dist, const float* __restrict__ xq,
             const float* __restrict__ cb) {
    __shared__ float rb[8];
    __shared__ unsigned smask[64];
    __shared__ int scand[MAXC];
    __shared__ float sd[MAXC];
    __shared__ int s_cnt;
    __shared__ float s_dmin;
    const int t = blockIdx.x, tid = threadIdx.x;
    const int wid = tid >> 5, lane = tid & 31;
    const float* dr = dist + (size_t)t * 2048;
    const float* xr = xq + (size_t)t * 768;

    float dl[8];
    float m = FLT_MAX;
    #pragma unroll
    for (int j = 0; j < 8; j++) {
        dl[j] = dr[tid + 256 * j];
        m = fminf(m, dl[j]);
    }
    #pragma unroll
    for (int o = 16; o > 0; o >>= 1) m = fminf(m, __shfl_xor_sync(0xffffffffu, m, o));
    if (tid < 64) smask[tid] = 0u;
    if (lane == 0) rb[wid] = m;
    __syncthreads();
    if (tid == 0) {
        float mm = rb[0];
        #pragma unroll
        for (int q = 1; q < 8; q++) mm = fminf(mm, rb[q]);
        s_dmin = mm;
    }
    __syncthreads();
    const float thr = s_dmin + WIN;
    #pragma unroll
    for (int j = 0; j < 8; j++)
        if (dl[j] <= thr) {
            int col = tid + 256 * j;
            atomicOr(&smask[col >> 5], 1u << (col & 31));
        }
    __syncthreads();
    if (tid == 0) {
        int cnt = 0;
        for (int w = 0; w < 64 && cnt < MAXC; w++) {
            unsigned bits = smask[w];
            while (bits && cnt < MAXC) {
                int bpos = __ffs(bits) - 1;
                bits &= bits - 1;
                scand[cnt++] = w * 32 + bpos;  // ascending col order
            }
        }
        s_cnt = cnt;
    }
    __syncthreads();
    const int cnt = s_cnt;
    // 8 candidates in parallel (one per warp), warp-shuffle dot
    for (int base = 0; base < cnt; base += 8) {
        int ci = base + wid;
        if (ci < cnt) {
            int col = scand[ci];
            const float* cr = cb + (size_t)col * 768;
            float p = 0.f;
            #pragma unroll 6
            for (int j = 0; j < 24; j++) {
                int k = lane + 32 * j;
                p = fmaf(xr[k], cr[k], p);
            }
            #pragma unroll
            for (int o = 16; o > 0; o >>= 1) p += __shfl_down_sync(0xffffffffu, p, o);
            if (lane == 0) sd[ci] = g_cbn[col] - 2.0f * p;
        }
        __syncthreads();
    }
    if (tid == 0) {
        unsigned long long best = ~0ull;
        int besti = 0;
        for (int ci = 0; ci < cnt; ci++) {
            unsigned long long pk =
                ((unsigned long long)fenc(sd[ci]) << 32) | (unsigned)scand[ci];
            if (pk < best) { best = pk; besti = ci; }
        }
        float d2nd = FLT_MAX;
        for (int ci = 0; ci < cnt; ci++)
            if (ci != besti) d2nd = fminf(d2nd, sd[ci]);
        if (cnt == 1 || (d2nd - sd[besti]) >= GAP_THR) {
            g_amin[t] = (unsigned long long)(unsigned)scand[besti];
            g_flag[t] = 0;
        } else {
            g_flag[t] = 1;
            g_ccnt[t] = cnt;
            for (int ci = 0; ci < cnt; ci++) g_cand[(size_t)t * MAXC + ci] = scand[ci];
        }
    }
}

// ---------------- pass 2: bit-exact replay of the R1 (passing) pipeline ----
#define SM2_FLOATS (2048 + 768 + 256 * 65)

__global__ __launch_bounds__(256)
void rescue2(const float* __restrict__ img, const float* __restrict__ w,
             const float* __restrict__ wb, const float* __restrict__ cb) {
    const int t = blockIdx.x;
    if (!g_flag[t]) return;
    extern __shared__ float sm2[];
    float* sA  = sm2;              // 2048
    float* sXq = sm2 + 2048;       // 768
    float* wt  = sm2 + 2048 + 768; // 256 x 65
    __shared__ unsigned long long pks[MAXC];
    const int tid = threadIdx.x;
    const int b = t >> 10, pi = (t >> 5) & 31, pj = t & 31;

    for (int k = tid; k < 2048; k += 256) {
        const float* ip = img + ((size_t)(b * 2048 + k) * 64 + 2 * pi) * 64 + 2 * pj;
        sA[k] = fmaxf(fmaxf(ip[0], ip[1]), fmaxf(ip[64], ip[65]));
    }
    __syncthreads();

    for (int cg = 0; cg < 3; cg++) {
        float acc = 0.f;
        for (int kt = 0; kt < 2048; kt += 64) {
            __syncthreads();
            #pragma unroll
            for (int q = 0; q < 16; q++) {
                int i4 = tid + 256 * q;
                int r = i4 >> 4;
                int kk4 = (i4 & 15) << 2;
                float4 v = *(const float4*)(w + (size_t)(cg * 256 + r) * 2048 + kt + kk4);
                wt[r * 65 + kk4 + 0] = v.x;
                wt[r * 65 + kk4 + 1] = v.y;
                wt[r * 65 + kk4 + 2] = v.z;
                wt[r * 65 + kk4 + 3] = v.w;
            }
            __syncthreads();
            #pragma unroll 8
            for (int kk = 0; kk < 64; kk++)
                acc = fmaf(sA[kt + kk], wt[tid * 65 + kk], acc);
        }
        sXq[cg * 256 + tid] = acc + wb[cg * 256 + tid];
        __syncthreads();
    }

    const int cnt = g_ccnt[t];
    if (tid < cnt) {
        int col = g_cand[(size_t)t * MAXC + tid];
        const float* cr = cb + (size_t)col * 768;
        float dot = 0.f;
        for (int k = 0; k < 768; k++) dot = fmaf(sXq[k], cr[k], dot);
        float d = g_cbn[col] - 2.0f * dot;
        pks[tid] = ((unsigned long long)fenc(d) << 32) | (unsigned)col;
    }
    __syncthreads();
    if (tid == 0) {
        unsigned long long best = pks[0];
        for (int ci = 1; ci < cnt; ci++)
            if (pks[ci] < best) best = pks[ci];
        g_amin[t] = best & 0xffffffffull;
    }
}

// ---------------- fused epilogue ----------------
__device__ __forceinline__ float blkSum(float v, float* rb, int tid) {
    #pragma unroll
    for (int o = 16; o > 0; o >>= 1) v += __shfl_down_sync(0xffffffffu, v, o);
    __syncthreads();
    if ((tid & 31) == 0) rb[tid >> 5] = v;
    __syncthreads();
    float r = 0.f;
    #pragma unroll
    for (int q = 0; q < 8; q++) r += rb[q];
    return r;
}

__global__ __launch_bounds__(256)
void epilogue_kernel(const int* __restrict__ vis_hw, const int* __restrict__ tpp,
                     const float* __restrict__ bern,
                     const float* __restrict__ gate_w, const float* __restrict__ gate_b,
                     const float* __restrict__ ln_g, const float* __restrict__ ln_b,
                     const float* __restrict__ mask_emb,
                     float* __restrict__ out, int out_size)
{
    __shared__ float rb[8];
    const int t = blockIdx.x, tid = threadIdx.x;
    const int b = t >> 10, pix = t & 1023, pi = pix >> 5, pj = pix & 31;
    const int imh = vis_hw[2 * b], imw = vis_hw[2 * b + 1];
    const bool rm = (32 * pi < imh), cm = (32 * pj < imw);
    const bool vm = rm && cm;
    const int nr = (imh + 31) >> 5, nc = (imw + 31) >> 5;
    const int idx = (int)(g_amin[t] & 0xffffffffull);

    const int tp = tpp[0];
    const int li = tp / 32, lj = tp % 32;
    const int idx_lab = (int)(g_amin[b * 1024 + li * 32 + lj] & 0xffffffffull);
    const bool vm_lab = (32 * li < imh) && (32 * lj < imw);
    const bool mi = vm && (bern[b] > 0.5f) && vm_lab && (idx == idx_lab);

    const float yv = cm ? (TWO_PI_F * (float)min(pi + 1, nr) / ((float)nr + 1e-6f)) : 0.f;
    const float xv = rm ? (TWO_PI_F * (float)min(pj + 1, nc) / ((float)nc + 1e-6f)) : 0.f;

    const float* emb = g_cbp + (size_t)idx * 768;
    const float* xq  = g_xq + (size_t)t * 768;

    float ev[3], qv[3];
    float s0 = 0.f, s1 = 0.f;
    #pragma unroll
    for (int q = 0; q < 3; q++) {
        int c = tid + 256 * q;
        float e = emb[c], x = xq[c];
        ev[q] = e; qv[q] = x;
        s0 += e * gate_w[c] + x * gate_w[768 + c];
        s1 += e * gate_w[1536 + c] + x * gate_w[2304 + c];
    }
    const float S0 = blkSum(s0, rb, tid) + gate_b[0];
    const float S1 = blkSum(s1, rb, tid) + gate_b[1];
    const float mx = fmaxf(S0, S1);
    const float e0 = expf(S0 - mx), e1 = expf(S1 - mx);
    const float inv = 1.0f / (e0 + e1);
    const float p0 = e0 * inv, p1 = e1 * inv;

    const float LCOEF = 0.04797052242f;  // 2*ln(10000)/384
    float f[3];
    #pragma unroll
    for (int q = 0; q < 3; q++) {
        int c = tid + 256 * q;
        int cc = c; float e;
        if (c < 384) { e = yv; } else { e = xv; cc = c - 384; }
        float invdim = expf(-LCOEF * (float)(cc >> 1));
        float val = e * invdim;
        float pos = (cc & 1) ? cosf(val) : sinf(val);
        float fu = mi ? mask_emb[c] : (ev[q] * p0 + qv[q] * p1);
        f[q] = fu + pos;
    }

    const float SUM = blkSum(f[0] + f[1] + f[2], rb, tid);
    const float mu = SUM * (1.0f / 768.0f);
    float d0 = f[0] - mu, d1 = f[1] - mu, d2 = f[2] - mu;
    const float SSQ = blkSum(d0 * d0 + d1 * d1 + d2 * d2, rb, tid);
    const float var = SSQ * (1.0f / 768.0f);
    const float rstd = rsqrtf(var + 1e-5f);

    #pragma unroll
    for (int q = 0; q < 3; q++) {
        int c = tid + 256 * q;
        out[(size_t)t * 768 + c] = (f[q] - mu) * rstd * ln_g[c] + ln_b[c];
    }

    if (tid == 0 && out_size >= 12615680) {
        out[12582912 + t] = vm ? 1.0f : 0.0f;
        out[12599296 + t] = mi ? (float)idx : -100.0f;
    }
}

// ---------------- launch ----------------
extern "C" void kernel_launch(void* const* d_in, const int* in_sizes, int n_in,
                              void* d_out, int out_size)
{
    const float* img      = (const float*)d_in[0];
    const int*   vis_hw   = (const int*)d_in[1];
    const int*   tmp_pos  = (const int*)d_in[2];
    const float* bern     = (const float*)d_in[3];
    const float* conv_w   = (const float*)d_in[4];
    const float* conv_b   = (const float*)d_in[5];
    const float* codebook = (const float*)d_in[6];
    const float* pos_w    = (const float*)d_in[7];
    const float* pos_b    = (const float*)d_in[8];
    const float* gate_w   = (const float*)d_in[9];
    const float* gate_b   = (const float*)d_in[10];
    const float* ln_g     = (const float*)d_in[11];
    const float* ln_b     = (const float*)d_in[12];
    const float* mask_emb = (const float*)d_in[13];
    float* out = (float*)d_out;

    void *pAhi, *pAlo, *pXq, *pXqhi;
    void *pWhi, *pWlo, *pCbhi, *pCblo, *pPwhi, *pPwlo, *pCbp;
    cudaGetSymbolAddress(&pAhi, g_Ahi);   cudaGetSymbolAddress(&pAlo, g_Alo);
    cudaGetSymbolAddress(&pXq, g_xq);     cudaGetSymbolAddress(&pXqhi, g_xqhi);
    cudaGetSymbolAddress(&pWhi, g_whi);   cudaGetSymbolAddress(&pWlo, g_wlo);
    cudaGetSymbolAddress(&pCbhi, g_cbhi); cudaGetSymbolAddress(&pCblo, g_cblo);
    cudaGetSymbolAddress(&pPwhi, g_pwhi); cudaGetSymbolAddress(&pPwlo, g_pwlo);
    cudaGetSymbolAddress(&pCbp, g_cbp);

    const int SM1 = NST * (2 * 1 * TILE_F) * 4;   // 1-split: 110592 B
    const int SM2 = NST * (2 * 2 * TILE_F) * 4;   // 2-split: 221184 B
    cudaFuncSetAttribute(mma_gemm<0, 1, 2>, cudaFuncAttributeMaxDynamicSharedMemorySize, SM2);
    cudaFuncSetAttribute(mma_gemm<0, 0, 2>, cudaFuncAttributeMaxDynamicSharedMemorySize, SM2);
    cudaFuncSetAttribute(mma_gemm<1, 0, 1>, cudaFuncAttributeMaxDynamicSharedMemorySize, SM1);
    cudaFuncSetAttribute(rescue2, cudaFuncAttributeMaxDynamicSharedMemorySize,
                         SM2_FLOATS * 4);

    pool_kernel<<<dim3(256, 32, 16), 256>>>(img);

    split_kernel<<<(768 * 2048 + 255) / 256, 256>>>(conv_w, (float*)pWhi, (float*)pWlo, 768 * 2048);
    split_kernel<<<(2048 * 768 + 255) / 256, 256>>>(codebook, (float*)pCbhi, (float*)pCblo, 2048 * 768);
    split_kernel<<<(768 * 768 + 255) / 256, 256>>>(pos_w, (float*)pPwhi, (float*)pPwlo, 768 * 768);

    cbn_kernel<<<N_CODES, 256>>>(codebook);

    // GEMM1: conv1x1  M=16384, N=768, K=2048 — 3-pass (+ tf32-hi of xq)
    mma_gemm<0, 1, 2><<<dim3(768 / 128, M_TOK / 128), 256, SM2>>>(
        (const float*)pAhi, (const float*)pAlo,
        (const float*)pWhi, (const float*)pWlo,
        (float*)pXq, (float*)pXqhi, conv_b, M_TOK, 768, 2048);

    // GEMM3: codebook @ pos_w^T  M=2048, N=768, K=768 — 3-pass
    mma_gemm<0, 0, 2><<<dim3(768 / 128, N_CODES / 128), 256, SM2>>>(
        (const float*)pCbhi, (const float*)pCblo,
        (const float*)pPwhi, (const float*)pPwlo,
        (float*)pCbp, nullptr, pos_b, N_CODES, 768, 768);

    // GEMM2: VQ screening distances -> g_Alo (reused) — 1-pass hi*hi
    mma_gemm<1, 0, 1><<<dim3(N_CODES / 128, M_TOK / 128), 256, SM1>>>(
        (const float*)pXqhi, nullptr,
        (const float*)pCbhi, nullptr,
        (float*)pAlo, nullptr, nullptr, M_TOK, N_CODES, 768);

    // pass 1: screen + classify; pass 2: R1-replica on ambiguous tokens
    rescue1<<<M_TOK, 256>>>((const float*)pAlo, (const float*)pXq, codebook);
    rescue2<<<M_TOK, 256, SM2_FLOATS * 4>>>(img, conv_w, conv_b, codebook);

    epilogue_kernel<<<M_TOK, 256>>>(vis_hw, tmp_pos, bern, gate_w, gate_b,
                                    ln_g, ln_b, mask_emb, out, out_size);
}

// round 17
// speedup vs baseline: 1.4682x; 1.4682x over previous
#include <cuda_runtime.h>
#include <cstdint>
#include <float.h>

#define TWO_PI_F 6.283185307179586f
#define M_TOK 16384
#define N_C   768
#define N_CODES 2048
#define MAXC 64
#define GAP_THR 0.15f
#define WIN 1.5f

// ---------------- scratch (device globals; no allocation allowed) ----------
__device__ float g_Ahi[(size_t)M_TOK * 2048];
__device__ float g_dist[(size_t)M_TOK * 2048];
__device__ float g_xq [(size_t)M_TOK * N_C];
__device__ float g_xqhi[(size_t)M_TOK * N_C];
__device__ float g_whi[(size_t)N_C * 2048];
__device__ float g_cbhi[(size_t)N_CODES * N_C];
__device__ float g_cblo[(size_t)N_CODES * N_C];
__device__ float g_pwhi[(size_t)N_C * N_C];
__device__ float g_pwlo[(size_t)N_C * N_C];
__device__ float g_cbp[(size_t)N_CODES * N_C];
__device__ float g_cbn[N_CODES];
__device__ unsigned long long g_amin[M_TOK];
__device__ int g_flag[M_TOK];
__device__ int g_ccnt[M_TOK];
__device__ int g_cand[(size_t)M_TOK * MAXC];

// ---------------- small helpers ----------------
__device__ __forceinline__ float tf32r(float v) {
    unsigned u; asm("cvt.rna.tf32.f32 %0, %1;" : "=r"(u) : "f"(v));
    return __uint_as_float(u);
}
__device__ __forceinline__ unsigned int fenc(float f) {
    unsigned int u = __float_as_uint(f);
    return (u & 0x80000000u) ? ~u : (u | 0x80000000u);
}

// ---------------- 2x2 maxpool + tf32 hi only ----------------
__global__ __launch_bounds__(256)
void pool_kernel(const float* __restrict__ img) {
    __shared__ float s[8 * 2 * 64];
    const int kchunk = blockIdx.x;
    const int hh = blockIdx.y;
    const int b  = blockIdx.z;
    const int tid = threadIdx.x;
    const int k0 = kchunk * 8;
    #pragma unroll
    for (int q = 0; q < 4; q++) {
        int l = tid + 256 * q;
        int x = l & 63, y = (l >> 6) & 1, kc = l >> 7;
        s[l] = img[((size_t)(b * 2048 + k0 + kc) * 64 + (2 * hh + y)) * 64 + x];
    }
    __syncthreads();
    const int kc = tid & 7, ww = tid >> 3;
    const float* p = &s[kc * 128];
    float v = fmaxf(fmaxf(p[2 * ww], p[2 * ww + 1]),
                    fmaxf(p[64 + 2 * ww], p[64 + 2 * ww + 1]));
    g_Ahi[(size_t)(b * 1024 + hh * 32 + ww) * 2048 + k0 + kc] = tf32r(v);
}

// ---------------- fp32 -> tf32 hi only ----------------
__global__ __launch_bounds__(256)
void splitH_kernel(const float* __restrict__ src, float* __restrict__ hi, int n) {
    int i = blockIdx.x * 256 + threadIdx.x;
    if (i < n) hi[i] = tf32r(src[i]);
}

// ---------------- fp32 -> (hi,lo) 2-way tf32 split ----------------
__global__ __launch_bounds__(256)
void split_kernel(const float* __restrict__ src, float* __restrict__ hi,
                  float* __restrict__ lo, int n) {
    int i = blockIdx.x * 256 + threadIdx.x;
    if (i < n) {
        float v = src[i];
        float h = tf32r(v);
        hi[i] = h;
        lo[i] = tf32r(v - h);
    }
}

// ---------------- codebook row norms (IDENTICAL to R1's kernel) ----------
__global__ __launch_bounds__(256)
void cbn_kernel(const float* __restrict__ cb) {
    __shared__ float rb[8];
    const int k = blockIdx.x, tid = threadIdx.x;
    float s = 0.f;
    for (int c = tid; c < 768; c += 256) {
        float v = cb[(size_t)k * 768 + c];
        s = fmaf(v, v, s);
    }
    #pragma unroll
    for (int o = 16; o > 0; o >>= 1) s += __shfl_down_sync(0xffffffffu, s, o);
    if ((tid & 31) == 0) rb[tid >> 5] = s;
    __syncthreads();
    if (tid == 0) {
        float t2 = 0.f;
        #pragma unroll
        for (int q = 0; q < 8; q++) t2 += rb[q];
        g_cbn[k] = t2;
    }
}

// ---------------- mma.sync multi-pass TF32 GEMM (2-stage, scalar LDS) ------
#define STRF 36
#define TILE_F (128 * STRF)

__device__ __forceinline__ void mma_tf32(float* d, const unsigned* a, const unsigned* b) {
    asm volatile(
        "mma.sync.aligned.m16n8k8.row.col.f32.tf32.tf32.f32 "
        "{%0,%1,%2,%3}, {%4,%5,%6,%7}, {%8,%9}, {%0,%1,%2,%3};"
        : "+f"(d[0]), "+f"(d[1]), "+f"(d[2]), "+f"(d[3])
        : "r"(a[0]), "r"(a[1]), "r"(a[2]), "r"(a[3]), "r"(b[0]), "r"(b[1]));
}

__device__ __forceinline__ void ld_tile_rm(uint32_t sdst, const float* __restrict__ g,
                                           int base_row, int K, int kt, int tid) {
    #pragma unroll
    for (int i = 0; i < 4; i++) {
        int idx = tid + 256 * i;
        int row = idx >> 3;
        int c = (idx & 7) * 4;
        const float* src = g + (size_t)(base_row + row) * K + kt * 32 + c;
        uint32_t dst = sdst + (uint32_t)(row * STRF + c) * 4u;
        asm volatile("cp.async.cg.shared.global [%0], [%1], 16;"
                     :: "r"(dst), "l"(src) : "memory");
    }
}

template<int MODE, int SPLIT, int NSPLIT, int MINB>
__global__ __launch_bounds__(256, MINB)
void mma_gemm(const float* __restrict__ A0, const float* __restrict__ A1,
              const float* __restrict__ B0, const float* __restrict__ B1,
              float* __restrict__ C, float* __restrict__ Chi,
              const float* __restrict__ bias, int M, int N, int K)
{
    extern __shared__ float smf[];
    const uint32_t sb = (uint32_t)__cvta_generic_to_shared(smf);
    const int STAGE_F = 2 * NSPLIT * TILE_F;

    const float* Ap[2] = {A0, A1};
    const float* Bp[2] = {B0, B1};

    const int tid = threadIdx.x;
    const int wid = tid >> 5, lane = tid & 31;
    const int g = lane >> 2, cid = lane & 3;
    const int wm = wid >> 2, wn = wid & 3;
    const int m0 = wm * 64, n0 = wn * 32;
    const int bm = blockIdx.y * 128, bn = blockIdx.x * 128;
    const int nk = K / 32;

    float acc[4][4][4];
    #pragma unroll
    for (int a = 0; a < 4; a++)
        #pragma unroll
        for (int b = 0; b < 4; b++)
            #pragma unroll
            for (int c = 0; c < 4; c++) acc[a][b][c] = 0.f;

    #pragma unroll
    for (int s = 0; s < 2; s++) {
        uint32_t st = sb + (uint32_t)(s * STAGE_F) * 4u;
        #pragma unroll
        for (int l = 0; l < NSPLIT; l++) {
            ld_tile_rm(st + (uint32_t)(l * TILE_F) * 4u,            Ap[l], bm, K, s, tid);
            ld_tile_rm(st + (uint32_t)((NSPLIT + l) * TILE_F) * 4u, Bp[l], bn, K, s, tid);
        }
        asm volatile("cp.async.commit_group;" ::: "memory");
    }

    for (int kt = 0; kt < nk; kt++) {
        asm volatile("cp.async.wait_group 1;" ::: "memory");
        __syncthreads();
        const float* st = smf + (kt & 1) * STAGE_F;

        #pragma unroll
        for (int k8 = 0; k8 < 4; k8++) {
            unsigned af[NSPLIT][4][4], bf[NSPLIT][4][2];
            #pragma unroll
            for (int l = 0; l < NSPLIT; l++) {
                const float* As = st + l * TILE_F;
                const float* Bs = st + (NSPLIT + l) * TILE_F;
                #pragma unroll
                for (int mt = 0; mt < 4; mt++) {
                    int ro = (m0 + mt * 16 + g) * STRF + k8 * 8 + cid;
                    af[l][mt][0] = __float_as_uint(As[ro]);
                    af[l][mt][1] = __float_as_uint(As[ro + 8 * STRF]);
                    af[l][mt][2] = __float_as_uint(As[ro + 4]);
                    af[l][mt][3] = __float_as_uint(As[ro + 8 * STRF + 4]);
                }
                #pragma unroll
                for (int nt = 0; nt < 4; nt++) {
                    int ro = (n0 + nt * 8 + g) * STRF + k8 * 8 + cid;
                    bf[l][nt][0] = __float_as_uint(Bs[ro]);
                    bf[l][nt][1] = __float_as_uint(Bs[ro + 4]);
                }
            }
            #pragma unroll
            for (int mt = 0; mt < 4; mt++)
                #pragma unroll
                for (int nt = 0; nt < 4; nt++) {
                    #pragma unroll
                    for (int ia = 0; ia < NSPLIT; ia++)
                        #pragma unroll
                        for (int ib = 0; ib < NSPLIT; ib++)
                            if (ia + ib <= NSPLIT - 1)
                                mma_tf32(acc[mt][nt], af[ia][mt], bf[ib][nt]);
                }
        }
        __syncthreads();
        if (kt + 2 < nk) {
            uint32_t st2 = sb + (uint32_t)((kt & 1) * STAGE_F) * 4u;
            #pragma unroll
            for (int l = 0; l < NSPLIT; l++) {
                ld_tile_rm(st2 + (uint32_t)(l * TILE_F) * 4u,            Ap[l], bm, K, kt + 2, tid);
                ld_tile_rm(st2 + (uint32_t)((NSPLIT + l) * TILE_F) * 4u, Bp[l], bn, K, kt + 2, tid);
            }
        }
        asm volatile("cp.async.commit_group;" ::: "memory");
    }

    #pragma unroll
    for (int mt = 0; mt < 4; mt++) {
        #pragma unroll
        for (int rv = 0; rv < 2; rv++) {
            int r = bm + m0 + mt * 16 + g + rv * 8;
            #pragma unroll
            for (int nt = 0; nt < 4; nt++) {
                int col = bn + n0 + nt * 8 + 2 * cid;
                if (MODE == 0) {
                    float v0 = acc[mt][nt][rv * 2 + 0] + bias[col];
                    float v1 = acc[mt][nt][rv * 2 + 1] + bias[col + 1];
                    float2 o; o.x = v0; o.y = v1;
                    *(float2*)(C + (size_t)r * N + col) = o;
                    if (SPLIT) {
                        float2 h;
                        h.x = tf32r(v0);
                        h.y = tf32r(v1);
                        *(float2*)(Chi + (size_t)r * N + col) = h;
                    }
                } else {
                    float2 o;
                    o.x = g_cbn[col]     - 2.0f * acc[mt][nt][rv * 2 + 0];
                    o.y = g_cbn[col + 1] - 2.0f * acc[mt][nt][rv * 2 + 1];
                    *(float2*)(C + (size_t)r * N + col) = o;
                }
            }
        }
    }
}

// ---------------- pass 1: screen + classify (warp-parallel candidates) -----
__global__ __launch_bounds__(256)
void rescue1(const float* __restrict__ dist, const float* __restrict__ xq,
             const float* __restrict__ cb) {
    __shared__ float rb[8];
    __shared__ unsigned smask[64];
    __shared__ int scand[MAXC];
    __shared__ float sd[MAXC];
    __shared__ int s_cnt;
    __shared__ float s_dmin;
    const int t = blockIdx.x, tid = threadIdx.x;
    const int wid = tid >> 5, lane = tid & 31;
    const float* dr = dist + (size_t)t * 2048;
    const float* xr = xq + (size_t)t * 768;

    float dl[8];
    float m = FLT_MAX;
    #pragma unroll
    for (int j = 0; j < 8; j++) {
        dl[j] = dr[tid + 256 * j];
        m = fminf(m, dl[j]);
    }
    #pragma unroll
    for (int o = 16; o > 0; o >>= 1) m = fminf(m, __shfl_xor_sync(0xffffffffu, m, o));
    if (tid < 64) smask[tid] = 0u;
    if (lane == 0) rb[wid] = m;
    __syncthreads();
    if (tid == 0) {
        float mm = rb[0];
        #pragma unroll
        for (int q = 1; q < 8; q++) mm = fminf(mm, rb[q]);
        s_dmin = mm;
    }
    __syncthreads();
    const float thr = s_dmin + WIN;
    #pragma unroll
    for (int j = 0; j < 8; j++)
        if (dl[j] <= thr) {
            int col = tid + 256 * j;
            atomicOr(&smask[col >> 5], 1u << (col & 31));
        }
    __syncthreads();
    if (tid == 0) {
        int cnt = 0;
        for (int w = 0; w < 64 && cnt < MAXC; w++) {
            unsigned bits = smask[w];
            while (bits && cnt < MAXC) {
                int bpos = __ffs(bits) - 1;
                bits &= bits - 1;
                scand[cnt++] = w * 32 + bpos;  // ascending col order
            }
        }
        s_cnt = cnt;
    }
    __syncthreads();
    const int cnt = s_cnt;
    for (int base = 0; base < cnt; base += 8) {
        int ci = base + wid;
        if (ci < cnt) {
            int col = scand[ci];
            const float* cr = cb + (size_t)col * 768;
            float p = 0.f;
            #pragma unroll 6
            for (int j = 0; j < 24; j++) {
                int k = lane + 32 * j;
                p = fmaf(xr[k], cr[k], p);
            }
            #pragma unroll
            for (int o = 16; o > 0; o >>= 1) p += __shfl_down_sync(0xffffffffu, p, o);
            if (lane == 0) sd[ci] = g_cbn[col] - 2.0f * p;
        }
        __syncthreads();
    }
    if (tid == 0) {
        unsigned long long best = ~0ull;
        int besti = 0;
        for (int ci = 0; ci < cnt; ci++) {
            unsigned long long pk =
                ((unsigned long long)fenc(sd[ci]) << 32) | (unsigned)scand[ci];
            if (pk < best) { best = pk; besti = ci; }
        }
        float d2nd = FLT_MAX;
        for (int ci = 0; ci < cnt; ci++)
            if (ci != besti) d2nd = fminf(d2nd, sd[ci]);
        if (cnt == 1 || (d2nd - sd[besti]) >= GAP_THR) {
            g_amin[t] = (unsigned long long)(unsigned)scand[besti];
            g_flag[t] = 0;
        } else {
            g_flag[t] = 1;
            g_ccnt[t] = cnt;
            for (int ci = 0; ci < cnt; ci++) g_cand[(size_t)t * MAXC + ci] = scand[ci];
        }
    }
}

// ---------------- pass 2: bit-exact replay of the R1 (passing) pipeline ----
#define SM2_FLOATS (2048 + 768 + 256 * 65)

__global__ __launch_bounds__(256)
void rescue2(const float* __restrict__ img, const float* __restrict__ w,
             const float* __restrict__ wb, const float* __restrict__ cb) {
    const int t = blockIdx.x;
    if (!g_flag[t]) return;
    extern __shared__ float sm2[];
    float* sA  = sm2;              // 2048
    float* sXq = sm2 + 2048;       // 768
    float* wt  = sm2 + 2048 + 768; // 256 x 65
    __shared__ unsigned long long pks[MAXC];
    const int tid = threadIdx.x;
    const int b = t >> 10, pi = (t >> 5) & 31, pj = t & 31;

    for (int k = tid; k < 2048; k += 256) {
        const float* ip = img + ((size_t)(b * 2048 + k) * 64 + 2 * pi) * 64 + 2 * pj;
        sA[k] = fmaxf(fmaxf(ip[0], ip[1]), fmaxf(ip[64], ip[65]));
    }
    __syncthreads();

    for (int cg = 0; cg < 3; cg++) {
        float acc = 0.f;
        for (int kt = 0; kt < 2048; kt += 64) {
            __syncthreads();
            #pragma unroll
            for (int q = 0; q < 16; q++) {
                int i4 = tid + 256 * q;
                int r = i4 >> 4;
                int kk4 = (i4 & 15) << 2;
                float4 v = *(const float4*)(w + (size_t)(cg * 256 + r) * 2048 + kt + kk4);
                wt[r * 65 + kk4 + 0] = v.x;
                wt[r * 65 + kk4 + 1] = v.y;
                wt[r * 65 + kk4 + 2] = v.z;
                wt[r * 65 + kk4 + 3] = v.w;
            }
            __syncthreads();
            #pragma unroll 8
            for (int kk = 0; kk < 64; kk++)
                acc = fmaf(sA[kt + kk], wt[tid * 65 + kk], acc);
        }
        sXq[cg * 256 + tid] = acc + wb[cg * 256 + tid];
        __syncthreads();
    }

    const int cnt = g_ccnt[t];
    if (tid < cnt) {
        int col = g_cand[(size_t)t * MAXC + tid];
        const float* cr = cb + (size_t)col * 768;
        float dot = 0.f;
        for (int k = 0; k < 768; k++) dot = fmaf(sXq[k], cr[k], dot);
        float d = g_cbn[col] - 2.0f * dot;
        pks[tid] = ((unsigned long long)fenc(d) << 32) | (unsigned)col;
    }
    __syncthreads();
    if (tid == 0) {
        unsigned long long best = pks[0];
        for (int ci = 1; ci < cnt; ci++)
            if (pks[ci] < best) best = pks[ci];
        g_amin[t] = best & 0xffffffffull;
    }
}

// ---------------- fused epilogue ----------------
__device__ __forceinline__ float blkSum(float v, float* rb, int tid) {
    #pragma unroll
    for (int o = 16; o > 0; o >>= 1) v += __shfl_down_sync(0xffffffffu, v, o);
    __syncthreads();
    if ((tid & 31) == 0) rb[tid >> 5] = v;
    __syncthreads();
    float r = 0.f;
    #pragma unroll
    for (int q = 0; q < 8; q++) r += rb[q];
    return r;
}

__global__ __launch_bounds__(256)
void epilogue_kernel(const int* __restrict__ vis_hw, const int* __restrict__ tpp,
                     const float* __restrict__ bern,
                     const float* __restrict__ gate_w, const float* __restrict__ gate_b,
                     const float* __restrict__ ln_g, const float* __restrict__ ln_b,
                     const float* __restrict__ mask_emb,
                     float* __restrict__ out, int out_size)
{
    __shared__ float rb[8];
    const int t = blockIdx.x, tid = threadIdx.x;
    const int b = t >> 10, pix = t & 1023, pi = pix >> 5, pj = pix & 31;
    const int imh = vis_hw[2 * b], imw = vis_hw[2 * b + 1];
    const bool rm = (32 * pi < imh), cm = (32 * pj < imw);
    const bool vm = rm && cm;
    const int nr = (imh + 31) >> 5, nc = (imw + 31) >> 5;
    const int idx = (int)(g_amin[t] & 0xffffffffull);

    const int tp = tpp[0];
    const int li = tp / 32, lj = tp % 32;
    const int idx_lab = (int)(g_amin[b * 1024 + li * 32 + lj] & 0xffffffffull);
    const bool vm_lab = (32 * li < imh) && (32 * lj < imw);
    const bool mi = vm && (bern[b] > 0.5f) && vm_lab && (idx == idx_lab);

    const float yv = cm ? (TWO_PI_F * (float)min(pi + 1, nr) / ((float)nr + 1e-6f)) : 0.f;
    const float xv = rm ? (TWO_PI_F * (float)min(pj + 1, nc) / ((float)nc + 1e-6f)) : 0.f;

    const float* emb = g_cbp + (size_t)idx * 768;
    const float* xq  = g_xq + (size_t)t * 768;

    float ev[3], qv[3];
    float s0 = 0.f, s1 = 0.f;
    #pragma unroll
    for (int q = 0; q < 3; q++) {
        int c = tid + 256 * q;
        float e = emb[c], x = xq[c];
        ev[q] = e; qv[q] = x;
        s0 += e * gate_w[c] + x * gate_w[768 + c];
        s1 += e * gate_w[1536 + c] + x * gate_w[2304 + c];
    }
    const float S0 = blkSum(s0, rb, tid) + gate_b[0];
    const float S1 = blkSum(s1, rb, tid) + gate_b[1];
    const float mx = fmaxf(S0, S1);
    const float e0 = expf(S0 - mx), e1 = expf(S1 - mx);
    const float inv = 1.0f / (e0 + e1);
    const float p0 = e0 * inv, p1 = e1 * inv;

    const float LCOEF = 0.04797052242f;  // 2*ln(10000)/384
    float f[3];
    #pragma unroll
    for (int q = 0; q < 3; q++) {
        int c = tid + 256 * q;
        int cc = c; float e;
        if (c < 384) { e = yv; } else { e = xv; cc = c - 384; }
        float invdim = expf(-LCOEF * (float)(cc >> 1));
        float val = e * invdim;
        float pos = (cc & 1) ? cosf(val) : sinf(val);
        float fu = mi ? mask_emb[c] : (ev[q] * p0 + qv[q] * p1);
        f[q] = fu + pos;
    }

    const float SUM = blkSum(f[0] + f[1] + f[2], rb, tid);
    const float mu = SUM * (1.0f / 768.0f);
    float d0 = f[0] - mu, d1 = f[1] - mu, d2 = f[2] - mu;
    const float SSQ = blkSum(d0 * d0 + d1 * d1 + d2 * d2, rb, tid);
    const float var = SSQ * (1.0f / 768.0f);
    const float rstd = rsqrtf(var + 1e-5f);

    #pragma unroll
    for (int q = 0; q < 3; q++) {
        int c = tid + 256 * q;
        out[(size_t)t * 768 + c] = (f[q] - mu) * rstd * ln_g[c] + ln_b[c];
    }

    if (tid == 0 && out_size >= 12615680) {
        out[12582912 + t] = vm ? 1.0f : 0.0f;
        out[12599296 + t] = mi ? (float)idx : -100.0f;
    }
}

// ---------------- launch ----------------
extern "C" void kernel_launch(void* const* d_in, const int* in_sizes, int n_in,
                              void* d_out, int out_size)
{
    const float* img      = (const float*)d_in[0];
    const int*   vis_hw   = (const int*)d_in[1];
    const int*   tmp_pos  = (const int*)d_in[2];
    const float* bern     = (const float*)d_in[3];
    const float* conv_w   = (const float*)d_in[4];
    const float* conv_b   = (const float*)d_in[5];
    const float* codebook = (const float*)d_in[6];
    const float* pos_w    = (const float*)d_in[7];
    const float* pos_b    = (const float*)d_in[8];
    const float* gate_w   = (const float*)d_in[9];
    const float* gate_b   = (const float*)d_in[10];
    const float* ln_g     = (const float*)d_in[11];
    const float* ln_b     = (const float*)d_in[12];
    const float* mask_emb = (const float*)d_in[13];
    float* out = (float*)d_out;

    void *pAhi, *pDist, *pXq, *pXqhi, *pWhi, *pCbhi, *pCblo, *pPwhi, *pPwlo, *pCbp;
    cudaGetSymbolAddress(&pAhi, g_Ahi);   cudaGetSymbolAddress(&pDist, g_dist);
    cudaGetSymbolAddress(&pXq, g_xq);     cudaGetSymbolAddress(&pXqhi, g_xqhi);
    cudaGetSymbolAddress(&pWhi, g_whi);   cudaGetSymbolAddress(&pCbhi, g_cbhi);
    cudaGetSymbolAddress(&pCblo, g_cblo);
    cudaGetSymbolAddress(&pPwhi, g_pwhi); cudaGetSymbolAddress(&pPwlo, g_pwlo);
    cudaGetSymbolAddress(&pCbp, g_cbp);

    const int SM1 = 2 * (2 * 1 * TILE_F) * 4;   // 1-split:  73728 B
    const int SM2 = 2 * (2 * 2 * TILE_F) * 4;   // 2-split: 147456 B
    cudaFuncSetAttribute(mma_gemm<0, 1, 1, 2>, cudaFuncAttributeMaxDynamicSharedMemorySize, SM1);
    cudaFuncSetAttribute(mma_gemm<0, 0, 2, 1>, cudaFuncAttributeMaxDynamicSharedMemorySize, SM2);
    cudaFuncSetAttribute(mma_gemm<1, 0, 1, 2>, cudaFuncAttributeMaxDynamicSharedMemorySize, SM1);
    cudaFuncSetAttribute(rescue2, cudaFuncAttributeMaxDynamicSharedMemorySize,
                         SM2_FLOATS * 4);

    pool_kernel<<<dim3(256, 32, 16), 256>>>(img);

    splitH_kernel<<<(768 * 2048 + 255) / 256, 256>>>(conv_w, (float*)pWhi, 768 * 2048);
    split_kernel<<<(2048 * 768 + 255) / 256, 256>>>(codebook, (float*)pCbhi, (float*)pCblo, 2048 * 768);
    split_kernel<<<(768 * 768 + 255) / 256, 256>>>(pos_w, (float*)pPwhi, (float*)pPwlo, 768 * 768);

    cbn_kernel<<<N_CODES, 256>>>(codebook);

    // GEMM1: conv1x1  M=16384, N=768, K=2048 — 1-pass tf32 (+ tf32-hi of xq)
    mma_gemm<0, 1, 1, 2><<<dim3(768 / 128, M_TOK / 128), 256, SM1>>>(
        (const float*)pAhi, nullptr,
        (const float*)pWhi, nullptr,
        (float*)pXq, (float*)pXqhi, conv_b, M_TOK, 768, 2048);

    // GEMM3: codebook @ pos_w^T  M=2048, N=768, K=768 — 3-pass (output path)
    mma_gemm<0, 0, 2, 1><<<dim3(768 / 128, N_CODES / 128), 256, SM2>>>(
        (const float*)pCbhi, (const float*)pCblo,
        (const float*)pPwhi, (const float*)pPwlo,
        (float*)pCbp, nullptr, pos_b, N_CODES, 768, 768);

    // GEMM2: VQ screening distances -> g_dist — 1-pass hi*hi
    mma_gemm<1, 0, 1, 2><<<dim3(N_CODES / 128, M_TOK / 128), 256, SM1>>>(
        (const float*)pXqhi, nullptr,
        (const float*)pCbhi, nullptr,
        (float*)pDist, nullptr, nullptr, M_TOK, N_CODES, 768);

    // pass 1: screen + classify; pass 2: R1-replica on ambiguous tokens
    rescue1<<<M_TOK, 256>>>((const float*)pDist, (const float*)pXq, codebook);
    rescue2<<<M_TOK, 256, SM2_FLOATS * 4>>>(img, conv_w, conv_b, codebook);

    epilogue_kernel<<<M_TOK, 256>>>(vis_hw, tmp_pos, bern, gate_w, gate_b,
                                    ln_g, ln_b, mask_emb, out, out_size);
}